// round 1
// baseline (speedup 1.0000x reference)
#include <cuda_runtime.h>
#include <math.h>

// Problem dims (fixed by the benchmark)
#define D_MODEL 768
#define NH      12
#define HDIM    64
#define C_CLS   50
#define S_SYN   4
#define B_BATCH 4
#define T_LEN   1024
#define R_ROWS  (C_CLS * S_SYN)      // 200
#define BZ      (B_BATCH * NH)       // 48

// -------- scratch (no allocation allowed) --------
__device__ float g_qproj[R_ROWS * D_MODEL];            // (c*4+s, d)
__device__ float g_kproj[B_BATCH * T_LEN * D_MODEL];   // tanh(H@WK+b)
__device__ float g_ktanh[B_BATCH * T_LEN * D_MODEL];   // tanh(H)
__device__ float g_wql [C_CLS * D_MODEL];              // ql@WV+b
__device__ float g_scores[BZ * R_ROWS * T_LEN];        // per (b,z): [200,1024]
__device__ float g_w  [BZ * C_CLS * T_LEN];            // combined softmax weights
__device__ float g_m2 [BZ * T_LEN * C_CLS];            // per (b,z): [1024,50]

// ============================================================
// Tiled SGEMM: C[M,N] = act(A[M,K] @ B[K,N] + bias[N])
// BM=BN=128, BK=8, 256 threads, 8x8 per thread. N,K multiples of 128/8.
// ============================================================
template <int ACT>
__global__ void __launch_bounds__(256) sgemm_bias_kernel(
    const float* __restrict__ A, const float* __restrict__ B,
    const float* __restrict__ bias, float* __restrict__ C,
    int M, int N, int K)
{
    __shared__ float As[8][128];
    __shared__ float Bs[8][128];
    const int tid  = threadIdx.x;
    const int bm   = blockIdx.y * 128, bn = blockIdx.x * 128;
    const int arow = tid >> 1, acol = (tid & 1) * 4;
    const int brow = tid >> 5, bcol = (tid & 31) * 4;
    const int tx   = tid & 15, ty = tid >> 4;

    float acc[8][8];
#pragma unroll
    for (int i = 0; i < 8; i++)
#pragma unroll
        for (int j = 0; j < 8; j++) acc[i][j] = 0.f;

    for (int k0 = 0; k0 < K; k0 += 8) {
        float4 av = make_float4(0.f, 0.f, 0.f, 0.f);
        if (bm + arow < M)
            av = *(const float4*)&A[(size_t)(bm + arow) * K + k0 + acol];
        As[acol + 0][arow] = av.x;
        As[acol + 1][arow] = av.y;
        As[acol + 2][arow] = av.z;
        As[acol + 3][arow] = av.w;
        *(float4*)&Bs[brow][bcol] =
            *(const float4*)&B[(size_t)(k0 + brow) * N + bn + bcol];
        __syncthreads();
#pragma unroll
        for (int k = 0; k < 8; k++) {
            float ra[8], rb[8];
            *(float4*)&ra[0] = *(float4*)&As[k][ty * 8];
            *(float4*)&ra[4] = *(float4*)&As[k][ty * 8 + 4];
            *(float4*)&rb[0] = *(float4*)&Bs[k][tx * 8];
            *(float4*)&rb[4] = *(float4*)&Bs[k][tx * 8 + 4];
#pragma unroll
            for (int i = 0; i < 8; i++)
#pragma unroll
                for (int j = 0; j < 8; j++)
                    acc[i][j] = fmaf(ra[i], rb[j], acc[i][j]);
        }
        __syncthreads();
    }

    float bv[8];
    *(float4*)&bv[0] = *(const float4*)&bias[bn + tx * 8];
    *(float4*)&bv[4] = *(const float4*)&bias[bn + tx * 8 + 4];
#pragma unroll
    for (int i = 0; i < 8; i++) {
        int row = bm + ty * 8 + i;
        if (row < M) {
            float o[8];
#pragma unroll
            for (int j = 0; j < 8; j++) {
                float v = acc[i][j] + bv[j];
                if (ACT == 1) v = tanhf(v);
                o[j] = v;
            }
            *(float4*)&C[(size_t)row * N + bn + tx * 8]     = *(float4*)&o[0];
            *(float4*)&C[(size_t)row * N + bn + tx * 8 + 4] = *(float4*)&o[4];
        }
    }
}

// ============================================================
// Batched "slab" GEMM over the 64-wide head slice:
//   per bz=(b,z):  C[m,n] = sum_{h<64} A[m, z*64+h] * B[n, z*64+h]
// A rows stride 768, B rows stride 768. BM=BN=64, one K pass.
// Used for: scores (A=qproj, B=kproj) and M2 (A=ktanh, B=wql).
// ============================================================
__global__ void __launch_bounds__(256) slab_gemm_kernel(
    const float* __restrict__ A, long sAb, long sAz,
    const float* __restrict__ B, long sBb, long sBz,
    float* __restrict__ C, int ldC, int M, int N)
{
    const int bz = blockIdx.z;
    const int b = bz / NH, z = bz % NH;
    const float* Ab = A + (size_t)b * sAb + (size_t)z * sAz;
    const float* Bb = B + (size_t)b * sBb + (size_t)z * sBz;
    float* Cb = C + (size_t)bz * M * ldC;

    __shared__ float Qs[64][68];   // [h][m], padded
    __shared__ float Ks[64][68];   // [h][n], padded

    const int tid = threadIdx.x;
    const int mbase = blockIdx.y * 64, nbase = blockIdx.x * 64;

#pragma unroll
    for (int i = 0; i < 4; i++) {
        int fl = tid + 256 * i;
        int row = fl >> 4;
        int hc = (fl & 15) * 4;
        float4 v = make_float4(0.f, 0.f, 0.f, 0.f);
        if (mbase + row < M)
            v = *(const float4*)&Ab[(size_t)(mbase + row) * D_MODEL + hc];
        Qs[hc + 0][row] = v.x; Qs[hc + 1][row] = v.y;
        Qs[hc + 2][row] = v.z; Qs[hc + 3][row] = v.w;
    }
#pragma unroll
    for (int i = 0; i < 4; i++) {
        int fl = tid + 256 * i;
        int row = fl >> 4;
        int hc = (fl & 15) * 4;
        float4 v = make_float4(0.f, 0.f, 0.f, 0.f);
        if (nbase + row < N)
            v = *(const float4*)&Bb[(size_t)(nbase + row) * D_MODEL + hc];
        Ks[hc + 0][row] = v.x; Ks[hc + 1][row] = v.y;
        Ks[hc + 2][row] = v.z; Ks[hc + 3][row] = v.w;
    }
    __syncthreads();

    const int tx = tid & 15, ty = tid >> 4;
    float acc[4][4];
#pragma unroll
    for (int i = 0; i < 4; i++)
#pragma unroll
        for (int j = 0; j < 4; j++) acc[i][j] = 0.f;

#pragma unroll
    for (int h = 0; h < 64; h++) {
        float ar[4], br[4];
        *(float4*)&ar[0] = *(float4*)&Qs[h][ty * 4];
        *(float4*)&br[0] = *(float4*)&Ks[h][tx * 4];
#pragma unroll
        for (int i = 0; i < 4; i++)
#pragma unroll
            for (int j = 0; j < 4; j++)
                acc[i][j] = fmaf(ar[i], br[j], acc[i][j]);
    }

#pragma unroll
    for (int i = 0; i < 4; i++) {
        int m = mbase + ty * 4 + i;
        if (m < M) {
#pragma unroll
            for (int j = 0; j < 4; j++) {
                int n = nbase + tx * 4 + j;
                if (n < N) Cb[(size_t)m * ldC + n] = acc[i][j];
            }
        }
    }
}

// ============================================================
// Softmax over t for 4 synonym rows, then combine into mean weights:
//   w[t] = 0.25 * sum_s exp(sc[s,t]-m_s)/l_s     (one block per (bz,c))
// ============================================================
__global__ void __launch_bounds__(128) softmax_combine_kernel(
    const float* __restrict__ scores, float* __restrict__ w)
{
    __shared__ float ex[4][1024];
    __shared__ float invl[4];
    const int blk = blockIdx.x;          // bz*50 + c
    const int bz = blk / C_CLS, c = blk % C_CLS;
    const int warp = threadIdx.x >> 5, lane = threadIdx.x & 31;

    const float* row = scores + ((size_t)bz * R_ROWS + c * 4 + warp) * T_LEN;

    float m = -INFINITY;
    for (int t = lane; t < T_LEN; t += 32) m = fmaxf(m, row[t]);
#pragma unroll
    for (int o = 16; o > 0; o >>= 1) m = fmaxf(m, __shfl_xor_sync(0xffffffffu, m, o));

    float ssum = 0.f;
    for (int t = lane; t < T_LEN; t += 32) {
        float e = expf(row[t] - m);
        ex[warp][t] = e;
        ssum += e;
    }
#pragma unroll
    for (int o = 16; o > 0; o >>= 1) ssum += __shfl_xor_sync(0xffffffffu, ssum, o);
    if (lane == 0) invl[warp] = 0.25f / ssum;
    __syncthreads();

    float* wr = w + ((size_t)bz * C_CLS + c) * T_LEN;
    for (int t = threadIdx.x; t < T_LEN; t += 128)
        wr[t] = ex[0][t] * invl[0] + ex[1][t] * invl[1]
              + ex[2][t] * invl[2] + ex[3][t] * invl[3];
}

// ============================================================
// tanh elementwise (Kh = tanh(H)), float4 vectorized
// ============================================================
__global__ void __launch_bounds__(256) tanh_kernel(
    const float* __restrict__ in, float* __restrict__ outp, int n4)
{
    int i = blockIdx.x * blockDim.x + threadIdx.x;
    if (i < n4) {
        float4 v = ((const float4*)in)[i];
        v.x = tanhf(v.x); v.y = tanhf(v.y);
        v.z = tanhf(v.z); v.w = tanhf(v.w);
        ((float4*)outp)[i] = v;
    }
}

// ============================================================
// Final: out[b,c] = sum_{z,t} w[bz,c,t] * m2[bz,t,c]
// ============================================================
__global__ void __launch_bounds__(256) final_out_kernel(
    const float* __restrict__ w, const float* __restrict__ m2,
    float* __restrict__ out)
{
    const int blk = blockIdx.x;           // b*50 + c
    const int b = blk / C_CLS, c = blk % C_CLS;
    float acc = 0.f;
    for (int idx = threadIdx.x; idx < NH * T_LEN; idx += 256) {
        int z = idx >> 10, t = idx & 1023;
        int bz = b * NH + z;
        float wv = w [((size_t)bz * C_CLS + c) * T_LEN + t];
        float mv = m2[((size_t)bz * T_LEN + t) * C_CLS + c];
        acc += wv * mv;
    }
    __shared__ float red[256];
    red[threadIdx.x] = acc;
    __syncthreads();
    for (int s = 128; s > 0; s >>= 1) {
        if (threadIdx.x < s) red[threadIdx.x] += red[threadIdx.x + s];
        __syncthreads();
    }
    if (threadIdx.x == 0) out[blk] = red[0];
}

// ============================================================
extern "C" void kernel_launch(void* const* d_in, const int* in_sizes, int n_in,
                              void* d_out, int out_size)
{
    const float* Q   = (const float*)d_in[0];
    const float* H   = (const float*)d_in[1];
    const float* ql  = (const float*)d_in[2];
    const float* WQw = (const float*)d_in[3];
    const float* WQb = (const float*)d_in[4];
    const float* WKw = (const float*)d_in[5];
    const float* WKb = (const float*)d_in[6];
    const float* WVw = (const float*)d_in[7];
    const float* WVb = (const float*)d_in[8];
    float* out = (float*)d_out;

    float *qproj, *kproj, *ktanh, *wql, *scores, *w, *m2;
    cudaGetSymbolAddress((void**)&qproj,  g_qproj);
    cudaGetSymbolAddress((void**)&kproj,  g_kproj);
    cudaGetSymbolAddress((void**)&ktanh,  g_ktanh);
    cudaGetSymbolAddress((void**)&wql,    g_wql);
    cudaGetSymbolAddress((void**)&scores, g_scores);
    cudaGetSymbolAddress((void**)&w,      g_w);
    cudaGetSymbolAddress((void**)&m2,     g_m2);

    // projections
    sgemm_bias_kernel<0><<<dim3(6, 2),  256>>>(Q,  WQw, WQb, qproj, R_ROWS, D_MODEL, D_MODEL);
    sgemm_bias_kernel<1><<<dim3(6, 32), 256>>>(H,  WKw, WKb, kproj, B_BATCH * T_LEN, D_MODEL, D_MODEL);
    sgemm_bias_kernel<0><<<dim3(6, 1),  256>>>(ql, WVw, WVb, wql,   C_CLS,  D_MODEL, D_MODEL);
    tanh_kernel<<<(B_BATCH * T_LEN * D_MODEL / 4 + 255) / 256, 256>>>(H, ktanh, B_BATCH * T_LEN * D_MODEL / 4);

    // scores[bz][r=200][t=1024] = qproj . kproj  (over 64-wide head slice)
    slab_gemm_kernel<<<dim3(16, 4, BZ), 256>>>(
        qproj, 0L, (long)HDIM,
        kproj, (long)T_LEN * D_MODEL, (long)HDIM,
        scores, T_LEN, R_ROWS, T_LEN);

    // softmax over t + combine synonyms into mean weights
    softmax_combine_kernel<<<BZ * C_CLS, 128>>>(scores, w);

    // m2[bz][t=1024][c=50] = ktanh . wql  (over 64-wide head slice)
    slab_gemm_kernel<<<dim3(1, 16, BZ), 256>>>(
        ktanh, (long)T_LEN * D_MODEL, (long)HDIM,
        wql, 0L, (long)HDIM,
        m2, C_CLS, T_LEN, C_CLS);

    // out[b,c] = sum_{z,t} w * m2
    final_out_kernel<<<B_BATCH * C_CLS, 256>>>(w, m2, out);
}

// round 2
// speedup vs baseline: 1.4412x; 1.4412x over previous
#include <cuda_runtime.h>
#include <math.h>
#include <stdint.h>

// Problem dims (fixed by the benchmark)
#define D_MODEL 768
#define NH      12
#define HDIM    64
#define C_CLS   50
#define S_SYN   4
#define B_BATCH 4
#define T_LEN   1024
#define R_ROWS  (C_CLS * S_SYN)      // 200
#define BZ      (B_BATCH * NH)       // 48

// -------- scratch (no allocation allowed) --------
__device__ float g_qproj[R_ROWS * D_MODEL];            // (c*4+s, d)
__device__ float g_kproj[B_BATCH * T_LEN * D_MODEL];   // tanh(H@WK+b)
__device__ float g_ktanh[B_BATCH * T_LEN * D_MODEL];   // tanh(H)
__device__ float g_wql [C_CLS * D_MODEL];              // ql@WV+b
__device__ float g_scores[BZ * R_ROWS * T_LEN];        // per (b,z): [200,1024]
__device__ float g_w  [BZ * C_CLS * T_LEN];            // combined softmax weights
__device__ float g_m2 [BZ * T_LEN * C_CLS];            // per (b,z): [1024,50]

// ============================================================
// tf32 helpers (3xTF32 split for fp32-accurate tensor-core GEMM)
// ============================================================
__device__ __forceinline__ void split_tf32(float x, uint32_t& hi, uint32_t& lo) {
    uint32_t h;
    asm("cvt.rna.tf32.f32 %0, %1;" : "=r"(h) : "f"(x));
    float l = x - __uint_as_float(h);
    uint32_t lb;
    asm("cvt.rna.tf32.f32 %0, %1;" : "=r"(lb) : "f"(l));
    hi = h; lo = lb;
}

__device__ __forceinline__ void mma_tf32(float* c, const uint32_t* a, const uint32_t* b) {
    asm volatile(
        "mma.sync.aligned.m16n8k8.row.col.f32.tf32.tf32.f32 "
        "{%0,%1,%2,%3}, {%4,%5,%6,%7}, {%8,%9}, {%0,%1,%2,%3};"
        : "+f"(c[0]), "+f"(c[1]), "+f"(c[2]), "+f"(c[3])
        : "r"(a[0]), "r"(a[1]), "r"(a[2]), "r"(a[3]), "r"(b[0]), "r"(b[1]));
}

// ============================================================
// Tensor-core GEMM (3xTF32): C[M,N] = act(A[M,K] @ B[K,N] + bias[N])
// Block 128x128, BK=32, 256 threads = 8 warps (4x2), warp tile 32x64.
// N multiple of 128, K multiple of 32. M ragged (guarded).
// ============================================================
#define ASTR 36
#define BSTR 136
template <int ACT>
__global__ void __launch_bounds__(256) gemm_tf32_kernel(
    const float* __restrict__ A, const float* __restrict__ B,
    const float* __restrict__ bias, float* __restrict__ C,
    int M, int N, int K)
{
    __shared__ float As[128][ASTR];
    __shared__ float Bs[32][BSTR];

    const int tid  = threadIdx.x;
    const int warp = tid >> 5, lane = tid & 31;
    const int wm = (warp >> 1) * 32;   // warp m offset (4 warps in m)
    const int wn = (warp & 1) * 64;    // warp n offset (2 warps in n)
    const int bm = blockIdx.y * 128, bn = blockIdx.x * 128;

    const int lrow = lane >> 2;        // 0..7
    const int lcol = lane & 3;         // 0..3

    float acc[2][8][4];
#pragma unroll
    for (int mi = 0; mi < 2; mi++)
#pragma unroll
        for (int ni = 0; ni < 8; ni++)
#pragma unroll
            for (int q = 0; q < 4; q++) acc[mi][ni][q] = 0.f;

    // gmem load indices
    const int ar = tid >> 1;           // row 0..127
    const int ac = (tid & 1) * 16;     // col 0 or 16
    const int br = tid >> 3;           // row 0..31
    const int bc = (tid & 7) * 4;      // col 0..28

    for (int k0 = 0; k0 < K; k0 += 32) {
        float4 av[4], bv[4];
        const bool arok = (bm + ar) < M;
#pragma unroll
        for (int i = 0; i < 4; i++) {
            av[i] = arok ? *(const float4*)&A[(size_t)(bm + ar) * K + k0 + ac + i * 4]
                         : make_float4(0.f, 0.f, 0.f, 0.f);
            bv[i] = *(const float4*)&B[(size_t)(k0 + br) * N + bn + bc + i * 32];
        }
        __syncthreads();
#pragma unroll
        for (int i = 0; i < 4; i++) {
            *(float4*)&As[ar][ac + i * 4] = av[i];
            *(float4*)&Bs[br][bc + i * 32] = bv[i];
        }
        __syncthreads();

#pragma unroll
        for (int ks = 0; ks < 32; ks += 8) {
            uint32_t ahi[2][4], alo[2][4];
#pragma unroll
            for (int mi = 0; mi < 2; mi++) {
                const int r0 = wm + mi * 16 + lrow;
                const int kc = ks + lcol;
                split_tf32(As[r0][kc],         ahi[mi][0], alo[mi][0]);
                split_tf32(As[r0 + 8][kc],     ahi[mi][1], alo[mi][1]);
                split_tf32(As[r0][kc + 4],     ahi[mi][2], alo[mi][2]);
                split_tf32(As[r0 + 8][kc + 4], ahi[mi][3], alo[mi][3]);
            }
#pragma unroll
            for (int ni = 0; ni < 8; ni++) {
                const int col = wn + ni * 8 + lrow;
                const int kr = ks + lcol;
                uint32_t bhi[2], blo[2];
                split_tf32(Bs[kr][col],     bhi[0], blo[0]);
                split_tf32(Bs[kr + 4][col], bhi[1], blo[1]);
#pragma unroll
                for (int mi = 0; mi < 2; mi++) {
                    mma_tf32(acc[mi][ni], ahi[mi], blo);
                    mma_tf32(acc[mi][ni], alo[mi], bhi);
                    mma_tf32(acc[mi][ni], ahi[mi], bhi);
                }
            }
        }
    }

    // epilogue: c0,c1 at (row, col..col+1), c2,c3 at (row+8, col..col+1)
#pragma unroll
    for (int mi = 0; mi < 2; mi++) {
        const int row = bm + wm + mi * 16 + lrow;
#pragma unroll
        for (int ni = 0; ni < 8; ni++) {
            const int col = bn + wn + ni * 8 + lcol * 2;
            const float b0 = bias[col], b1 = bias[col + 1];
            if (row < M) {
                float v0 = acc[mi][ni][0] + b0, v1 = acc[mi][ni][1] + b1;
                if (ACT == 1) { v0 = tanhf(v0); v1 = tanhf(v1); }
                *(float2*)&C[(size_t)row * N + col] = make_float2(v0, v1);
            }
            if (row + 8 < M) {
                float v2 = acc[mi][ni][2] + b0, v3 = acc[mi][ni][3] + b1;
                if (ACT == 1) { v2 = tanhf(v2); v3 = tanhf(v3); }
                *(float2*)&C[(size_t)(row + 8) * N + col] = make_float2(v2, v3);
            }
        }
    }
}

// ============================================================
// Batched "slab" GEMM over the 64-wide head slice:
//   per bz=(b,z):  C[m,n] = sum_{h<64} A[m, z*64+h] * B[n, z*64+h]
// ============================================================
__global__ void __launch_bounds__(256) slab_gemm_kernel(
    const float* __restrict__ A, long sAb, long sAz,
    const float* __restrict__ B, long sBb, long sBz,
    float* __restrict__ C, int ldC, int M, int N)
{
    const int bz = blockIdx.z;
    const int b = bz / NH, z = bz % NH;
    const float* Ab = A + (size_t)b * sAb + (size_t)z * sAz;
    const float* Bb = B + (size_t)b * sBb + (size_t)z * sBz;
    float* Cb = C + (size_t)bz * M * ldC;

    __shared__ float Qs[64][68];   // [h][m], padded
    __shared__ float Ks[64][68];   // [h][n], padded

    const int tid = threadIdx.x;
    const int mbase = blockIdx.y * 64, nbase = blockIdx.x * 64;

#pragma unroll
    for (int i = 0; i < 4; i++) {
        int fl = tid + 256 * i;
        int row = fl >> 4;
        int hc = (fl & 15) * 4;
        float4 v = make_float4(0.f, 0.f, 0.f, 0.f);
        if (mbase + row < M)
            v = *(const float4*)&Ab[(size_t)(mbase + row) * D_MODEL + hc];
        Qs[hc + 0][row] = v.x; Qs[hc + 1][row] = v.y;
        Qs[hc + 2][row] = v.z; Qs[hc + 3][row] = v.w;
    }
#pragma unroll
    for (int i = 0; i < 4; i++) {
        int fl = tid + 256 * i;
        int row = fl >> 4;
        int hc = (fl & 15) * 4;
        float4 v = make_float4(0.f, 0.f, 0.f, 0.f);
        if (nbase + row < N)
            v = *(const float4*)&Bb[(size_t)(nbase + row) * D_MODEL + hc];
        Ks[hc + 0][row] = v.x; Ks[hc + 1][row] = v.y;
        Ks[hc + 2][row] = v.z; Ks[hc + 3][row] = v.w;
    }
    __syncthreads();

    const int tx = tid & 15, ty = tid >> 4;
    float acc[4][4];
#pragma unroll
    for (int i = 0; i < 4; i++)
#pragma unroll
        for (int j = 0; j < 4; j++) acc[i][j] = 0.f;

#pragma unroll
    for (int h = 0; h < 64; h++) {
        float ar[4], br[4];
        *(float4*)&ar[0] = *(float4*)&Qs[h][ty * 4];
        *(float4*)&br[0] = *(float4*)&Ks[h][tx * 4];
#pragma unroll
        for (int i = 0; i < 4; i++)
#pragma unroll
            for (int j = 0; j < 4; j++)
                acc[i][j] = fmaf(ar[i], br[j], acc[i][j]);
    }

#pragma unroll
    for (int i = 0; i < 4; i++) {
        int m = mbase + ty * 4 + i;
        if (m < M) {
#pragma unroll
            for (int j = 0; j < 4; j++) {
                int n = nbase + tx * 4 + j;
                if (n < N) Cb[(size_t)m * ldC + n] = acc[i][j];
            }
        }
    }
}

// ============================================================
// Softmax over t for 4 synonym rows, then combine into mean weights
// ============================================================
__global__ void __launch_bounds__(128) softmax_combine_kernel(
    const float* __restrict__ scores, float* __restrict__ w)
{
    __shared__ float ex[4][1024];
    __shared__ float invl[4];
    const int blk = blockIdx.x;          // bz*50 + c
    const int bz = blk / C_CLS, c = blk % C_CLS;
    const int warp = threadIdx.x >> 5, lane = threadIdx.x & 31;

    const float* row = scores + ((size_t)bz * R_ROWS + c * 4 + warp) * T_LEN;

    float m = -INFINITY;
    for (int t = lane; t < T_LEN; t += 32) m = fmaxf(m, row[t]);
#pragma unroll
    for (int o = 16; o > 0; o >>= 1) m = fmaxf(m, __shfl_xor_sync(0xffffffffu, m, o));

    float ssum = 0.f;
    for (int t = lane; t < T_LEN; t += 32) {
        float e = expf(row[t] - m);
        ex[warp][t] = e;
        ssum += e;
    }
#pragma unroll
    for (int o = 16; o > 0; o >>= 1) ssum += __shfl_xor_sync(0xffffffffu, ssum, o);
    if (lane == 0) invl[warp] = 0.25f / ssum;
    __syncthreads();

    float* wr = w + ((size_t)bz * C_CLS + c) * T_LEN;
    for (int t = threadIdx.x; t < T_LEN; t += 128)
        wr[t] = ex[0][t] * invl[0] + ex[1][t] * invl[1]
              + ex[2][t] * invl[2] + ex[3][t] * invl[3];
}

// ============================================================
// tanh elementwise (Kh = tanh(H)), float4 vectorized
// ============================================================
__global__ void __launch_bounds__(256) tanh_kernel(
    const float* __restrict__ in, float* __restrict__ outp, int n4)
{
    int i = blockIdx.x * blockDim.x + threadIdx.x;
    if (i < n4) {
        float4 v = ((const float4*)in)[i];
        v.x = tanhf(v.x); v.y = tanhf(v.y);
        v.z = tanhf(v.z); v.w = tanhf(v.w);
        ((float4*)outp)[i] = v;
    }
}

// ============================================================
// Final: out[b,c] = sum_{z,t} w[bz,c,t] * m2[bz,t,c]
// ============================================================
__global__ void __launch_bounds__(256) final_out_kernel(
    const float* __restrict__ w, const float* __restrict__ m2,
    float* __restrict__ out)
{
    const int blk = blockIdx.x;           // b*50 + c
    const int b = blk / C_CLS, c = blk % C_CLS;
    float acc = 0.f;
    for (int idx = threadIdx.x; idx < NH * T_LEN; idx += 256) {
        int z = idx >> 10, t = idx & 1023;
        int bz = b * NH + z;
        float wv = w [((size_t)bz * C_CLS + c) * T_LEN + t];
        float mv = m2[((size_t)bz * T_LEN + t) * C_CLS + c];
        acc += wv * mv;
    }
    __shared__ float red[256];
    red[threadIdx.x] = acc;
    __syncthreads();
    for (int s = 128; s > 0; s >>= 1) {
        if (threadIdx.x < s) red[threadIdx.x] += red[threadIdx.x + s];
        __syncthreads();
    }
    if (threadIdx.x == 0) out[blk] = red[0];
}

// ============================================================
extern "C" void kernel_launch(void* const* d_in, const int* in_sizes, int n_in,
                              void* d_out, int out_size)
{
    const float* Q   = (const float*)d_in[0];
    const float* H   = (const float*)d_in[1];
    const float* ql  = (const float*)d_in[2];
    const float* WQw = (const float*)d_in[3];
    const float* WQb = (const float*)d_in[4];
    const float* WKw = (const float*)d_in[5];
    const float* WKb = (const float*)d_in[6];
    const float* WVw = (const float*)d_in[7];
    const float* WVb = (const float*)d_in[8];
    float* out = (float*)d_out;

    float *qproj, *kproj, *ktanh, *wql, *scores, *w, *m2;
    cudaGetSymbolAddress((void**)&qproj,  g_qproj);
    cudaGetSymbolAddress((void**)&kproj,  g_kproj);
    cudaGetSymbolAddress((void**)&ktanh,  g_ktanh);
    cudaGetSymbolAddress((void**)&wql,    g_wql);
    cudaGetSymbolAddress((void**)&scores, g_scores);
    cudaGetSymbolAddress((void**)&w,      g_w);
    cudaGetSymbolAddress((void**)&m2,     g_m2);

    // projections on tensor cores (3xTF32, fp32-accurate)
    gemm_tf32_kernel<0><<<dim3(6, 2),  256>>>(Q,  WQw, WQb, qproj, R_ROWS, D_MODEL, D_MODEL);
    gemm_tf32_kernel<1><<<dim3(6, 32), 256>>>(H,  WKw, WKb, kproj, B_BATCH * T_LEN, D_MODEL, D_MODEL);
    gemm_tf32_kernel<0><<<dim3(6, 1),  256>>>(ql, WVw, WVb, wql,   C_CLS,  D_MODEL, D_MODEL);
    tanh_kernel<<<(B_BATCH * T_LEN * D_MODEL / 4 + 255) / 256, 256>>>(H, ktanh, B_BATCH * T_LEN * D_MODEL / 4);

    // scores[bz][r=200][t=1024] = qproj . kproj  (over 64-wide head slice)
    slab_gemm_kernel<<<dim3(16, 4, BZ), 256>>>(
        qproj, 0L, (long)HDIM,
        kproj, (long)T_LEN * D_MODEL, (long)HDIM,
        scores, T_LEN, R_ROWS, T_LEN);

    // softmax over t + combine synonyms into mean weights
    softmax_combine_kernel<<<BZ * C_CLS, 128>>>(scores, w);

    // m2[bz][t=1024][c=50] = ktanh . wql  (over 64-wide head slice)
    slab_gemm_kernel<<<dim3(1, 16, BZ), 256>>>(
        ktanh, (long)T_LEN * D_MODEL, (long)HDIM,
        wql, 0L, (long)HDIM,
        m2, C_CLS, T_LEN, C_CLS);

    // out[b,c] = sum_{z,t} w * m2
    final_out_kernel<<<B_BATCH * C_CLS, 256>>>(w, m2, out);
}

// round 3
// speedup vs baseline: 1.5777x; 1.0947x over previous
#include <cuda_runtime.h>
#include <math.h>
#include <stdint.h>

// Problem dims (fixed by the benchmark)
#define D_MODEL 768
#define NH      12
#define HDIM    64
#define C_CLS   50
#define S_SYN   4
#define B_BATCH 4
#define T_LEN   1024
#define R_ROWS  (C_CLS * S_SYN)      // 200
#define BZ      (B_BATCH * NH)       // 48

// -------- scratch (no allocation allowed) --------
__device__ float g_qproj[R_ROWS * D_MODEL];            // (c*4+s, d)
__device__ float g_kproj[B_BATCH * T_LEN * D_MODEL];   // tanh(H@WK+b)
__device__ float g_ktanh[B_BATCH * T_LEN * D_MODEL];   // tanh(H)
__device__ float g_wql [C_CLS * D_MODEL];              // ql@WV+b
__device__ float g_scores[BZ * R_ROWS * T_LEN];        // per (b,z): [200,1024]
__device__ float g_w  [BZ * C_CLS * T_LEN];            // combined softmax weights
__device__ float g_m2 [BZ * T_LEN * C_CLS];            // per (b,z): [1024,50]

// ============================================================
// tf32 helpers
// ============================================================
__device__ __forceinline__ void split_tf32(float x, uint32_t& hi, uint32_t& lo) {
    uint32_t h;
    asm("cvt.rna.tf32.f32 %0, %1;" : "=r"(h) : "f"(x));
    float l = x - __uint_as_float(h);
    uint32_t lb;
    asm("cvt.rna.tf32.f32 %0, %1;" : "=r"(lb) : "f"(l));
    hi = h; lo = lb;
}

__device__ __forceinline__ void split4(float4 v, uint32_t* hi, uint32_t* lo) {
    split_tf32(v.x, hi[0], lo[0]);
    split_tf32(v.y, hi[1], lo[1]);
    split_tf32(v.z, hi[2], lo[2]);
    split_tf32(v.w, hi[3], lo[3]);
}

__device__ __forceinline__ void mma_tf32(float* c, const uint32_t* a, const uint32_t* b) {
    asm volatile(
        "mma.sync.aligned.m16n8k8.row.col.f32.tf32.tf32.f32 "
        "{%0,%1,%2,%3}, {%4,%5,%6,%7}, {%8,%9}, {%0,%1,%2,%3};"
        : "+f"(c[0]), "+f"(c[1]), "+f"(c[2]), "+f"(c[3])
        : "r"(a[0]), "r"(a[1]), "r"(a[2]), "r"(a[3]), "r"(b[0]), "r"(b[1]));
}

// ============================================================
// Projection GEMM (3xTF32, pre-split smem, prefetched):
//   C[M,N] = act(A[M,K] @ B[K,N] + bias[N])
// Block 128x128, BK=32, 256 threads = 8 warps (4x2), warp tile 32x64.
// N,K multiples of 128/32. M ragged. Dynamic smem = 71680 B.
// ============================================================
#define ASTR 36
#define BSTR 136
#define GEMM_SMEM ((2 * 128 * ASTR + 2 * 32 * BSTR) * 4)

template <int ACT>
__global__ void __launch_bounds__(256) gemm_tf32_kernel(
    const float* __restrict__ A, const float* __restrict__ B,
    const float* __restrict__ bias, float* __restrict__ C,
    int M, int N, int K)
{
    extern __shared__ uint32_t sm[];
    uint32_t* As_hi = sm;                       // [128][ASTR]
    uint32_t* As_lo = As_hi + 128 * ASTR;
    uint32_t* Bs_hi = As_lo + 128 * ASTR;       // [32][BSTR]
    uint32_t* Bs_lo = Bs_hi + 32 * BSTR;

    const int tid  = threadIdx.x;
    const int warp = tid >> 5, lane = tid & 31;
    const int wm = (warp >> 1) * 32;
    const int wn = (warp & 1) * 64;
    const int bm = blockIdx.y * 128, bn = blockIdx.x * 128;
    const int lrow = lane >> 2, lcol = lane & 3;

    float acc[2][8][4];
#pragma unroll
    for (int mi = 0; mi < 2; mi++)
#pragma unroll
        for (int ni = 0; ni < 8; ni++)
#pragma unroll
            for (int q = 0; q < 4; q++) acc[mi][ni][q] = 0.f;

    const int ar = tid >> 1, ac = (tid & 1) * 16;   // A: row 0..127, col 0/16
    const int br = tid >> 3, bc = (tid & 7) * 4;    // B: row 0..31, col 0..28
    const bool arok = (bm + ar) < M;

    float4 av[4], bv[4];
#pragma unroll
    for (int i = 0; i < 4; i++) {
        av[i] = arok ? *(const float4*)&A[(size_t)(bm + ar) * K + ac + i * 4]
                     : make_float4(0.f, 0.f, 0.f, 0.f);
        bv[i] = *(const float4*)&B[(size_t)br * N + bn + bc + i * 32];
    }

    for (int k0 = 0; k0 < K; k0 += 32) {
        // split current regs into smem
#pragma unroll
        for (int i = 0; i < 4; i++) {
            uint32_t hi[4], lo[4];
            split4(av[i], hi, lo);
            *(uint4*)&As_hi[ar * ASTR + ac + i * 4] = *(uint4*)hi;
            *(uint4*)&As_lo[ar * ASTR + ac + i * 4] = *(uint4*)lo;
            split4(bv[i], hi, lo);
            *(uint4*)&Bs_hi[br * BSTR + bc + i * 32] = *(uint4*)hi;
            *(uint4*)&Bs_lo[br * BSTR + bc + i * 32] = *(uint4*)lo;
        }
        __syncthreads();

        // prefetch next tile
        if (k0 + 32 < K) {
#pragma unroll
            for (int i = 0; i < 4; i++) {
                av[i] = arok ? *(const float4*)&A[(size_t)(bm + ar) * K + k0 + 32 + ac + i * 4]
                             : make_float4(0.f, 0.f, 0.f, 0.f);
                bv[i] = *(const float4*)&B[(size_t)(k0 + 32 + br) * N + bn + bc + i * 32];
            }
        }

#pragma unroll
        for (int ks = 0; ks < 32; ks += 8) {
            uint32_t ahi[2][4], alo[2][4];
#pragma unroll
            for (int mi = 0; mi < 2; mi++) {
                const int r0 = wm + mi * 16 + lrow;
                const int kc = ks + lcol;
                ahi[mi][0] = As_hi[r0 * ASTR + kc];
                alo[mi][0] = As_lo[r0 * ASTR + kc];
                ahi[mi][1] = As_hi[(r0 + 8) * ASTR + kc];
                alo[mi][1] = As_lo[(r0 + 8) * ASTR + kc];
                ahi[mi][2] = As_hi[r0 * ASTR + kc + 4];
                alo[mi][2] = As_lo[r0 * ASTR + kc + 4];
                ahi[mi][3] = As_hi[(r0 + 8) * ASTR + kc + 4];
                alo[mi][3] = As_lo[(r0 + 8) * ASTR + kc + 4];
            }
#pragma unroll
            for (int ni = 0; ni < 8; ni++) {
                const int col = wn + ni * 8 + lrow;
                const int kr = ks + lcol;
                uint32_t bhi[2], blo[2];
                bhi[0] = Bs_hi[kr * BSTR + col];
                blo[0] = Bs_lo[kr * BSTR + col];
                bhi[1] = Bs_hi[(kr + 4) * BSTR + col];
                blo[1] = Bs_lo[(kr + 4) * BSTR + col];
#pragma unroll
                for (int mi = 0; mi < 2; mi++) {
                    mma_tf32(acc[mi][ni], ahi[mi], blo);
                    mma_tf32(acc[mi][ni], alo[mi], bhi);
                    mma_tf32(acc[mi][ni], ahi[mi], bhi);
                }
            }
        }
        __syncthreads();
    }

#pragma unroll
    for (int mi = 0; mi < 2; mi++) {
        const int row = bm + wm + mi * 16 + lrow;
#pragma unroll
        for (int ni = 0; ni < 8; ni++) {
            const int col = bn + wn + ni * 8 + lcol * 2;
            const float b0 = bias[col], b1 = bias[col + 1];
            if (row < M) {
                float v0 = acc[mi][ni][0] + b0, v1 = acc[mi][ni][1] + b1;
                if (ACT == 1) { v0 = tanhf(v0); v1 = tanhf(v1); }
                *(float2*)&C[(size_t)row * N + col] = make_float2(v0, v1);
            }
            if (row + 8 < M) {
                float v2 = acc[mi][ni][2] + b0, v3 = acc[mi][ni][3] + b1;
                if (ACT == 1) { v2 = tanhf(v2); v3 = tanhf(v3); }
                *(float2*)&C[(size_t)(row + 8) * N + col] = make_float2(v2, v3);
            }
        }
    }
}

// ============================================================
// Scores GEMM on tensor cores (3xTF32):
//  per bz: C[m,t] = sum_{h<64} qproj[m, z*64+h] * kproj[b,t, z*64+h]
// Block 64x128, BK=64 (single pass), 256 threads = 8 warps (2x4),
// warp tile 32x32. A and B both stored [row][k] (k-minor, stride 68).
// Dynamic smem = 104448 B.
// ============================================================
#define SSTR 68
#define SC_SMEM ((2 * 64 * SSTR + 2 * 128 * SSTR) * 4)

__global__ void __launch_bounds__(256) scores_tf32_kernel(
    const float* __restrict__ qproj, const float* __restrict__ kproj,
    float* __restrict__ scores)
{
    extern __shared__ uint32_t sm[];
    uint32_t* As_hi = sm;                        // [64][SSTR]  (m, h)
    uint32_t* As_lo = As_hi + 64 * SSTR;
    uint32_t* Bt_hi = As_lo + 64 * SSTR;         // [128][SSTR] (t, h)
    uint32_t* Bt_lo = Bt_hi + 128 * SSTR;

    const int bz = blockIdx.z;
    const int b = bz / NH, z = bz % NH;
    const float* Ab = qproj + (size_t)z * HDIM;
    const float* Bb = kproj + (size_t)b * T_LEN * D_MODEL + (size_t)z * HDIM;
    float* Cb = g_scores + (size_t)bz * R_ROWS * T_LEN;
    (void)scores;

    const int tid  = threadIdx.x;
    const int warp = tid >> 5, lane = tid & 31;
    const int wm = (warp >> 2) * 32;     // 2 warp-rows
    const int wn = (warp & 3) * 32;      // 4 warp-cols
    const int mbase = blockIdx.y * 64, nbase = blockIdx.x * 128;
    const int lrow = lane >> 2, lcol = lane & 3;

    // load A tile: 64 rows x 64 h
    {
        const int row = tid >> 2, colb = (tid & 3) * 16;
        const bool ok = (mbase + row) < R_ROWS;
#pragma unroll
        for (int i = 0; i < 4; i++) {
            float4 v = ok ? *(const float4*)&Ab[(size_t)(mbase + row) * D_MODEL + colb + i * 4]
                          : make_float4(0.f, 0.f, 0.f, 0.f);
            uint32_t hi[4], lo[4];
            split4(v, hi, lo);
            *(uint4*)&As_hi[row * SSTR + colb + i * 4] = *(uint4*)hi;
            *(uint4*)&As_lo[row * SSTR + colb + i * 4] = *(uint4*)lo;
        }
    }
    // load B tile: 128 rows (t) x 64 h, natural layout
    {
        const int r0 = tid >> 2, colb = (tid & 3) * 16;
#pragma unroll
        for (int half = 0; half < 2; half++) {
            const int row = r0 + half * 64;
#pragma unroll
            for (int i = 0; i < 4; i++) {
                float4 v = *(const float4*)&Bb[(size_t)(nbase + row) * D_MODEL + colb + i * 4];
                uint32_t hi[4], lo[4];
                split4(v, hi, lo);
                *(uint4*)&Bt_hi[row * SSTR + colb + i * 4] = *(uint4*)hi;
                *(uint4*)&Bt_lo[row * SSTR + colb + i * 4] = *(uint4*)lo;
            }
        }
    }
    __syncthreads();

    float acc[2][4][4];
#pragma unroll
    for (int mi = 0; mi < 2; mi++)
#pragma unroll
        for (int ni = 0; ni < 4; ni++)
#pragma unroll
            for (int q = 0; q < 4; q++) acc[mi][ni][q] = 0.f;

#pragma unroll
    for (int ks = 0; ks < 64; ks += 8) {
        uint32_t ahi[2][4], alo[2][4];
#pragma unroll
        for (int mi = 0; mi < 2; mi++) {
            const int r0 = wm + mi * 16 + lrow;
            const int kc = ks + lcol;
            ahi[mi][0] = As_hi[r0 * SSTR + kc];
            alo[mi][0] = As_lo[r0 * SSTR + kc];
            ahi[mi][1] = As_hi[(r0 + 8) * SSTR + kc];
            alo[mi][1] = As_lo[(r0 + 8) * SSTR + kc];
            ahi[mi][2] = As_hi[r0 * SSTR + kc + 4];
            alo[mi][2] = As_lo[r0 * SSTR + kc + 4];
            ahi[mi][3] = As_hi[(r0 + 8) * SSTR + kc + 4];
            alo[mi][3] = As_lo[(r0 + 8) * SSTR + kc + 4];
        }
#pragma unroll
        for (int ni = 0; ni < 4; ni++) {
            const int col = wn + ni * 8 + lrow;   // t index
            const int kr = ks + lcol;
            uint32_t bhi[2], blo[2];
            bhi[0] = Bt_hi[col * SSTR + kr];
            blo[0] = Bt_lo[col * SSTR + kr];
            bhi[1] = Bt_hi[col * SSTR + kr + 4];
            blo[1] = Bt_lo[col * SSTR + kr + 4];
#pragma unroll
            for (int mi = 0; mi < 2; mi++) {
                mma_tf32(acc[mi][ni], ahi[mi], blo);
                mma_tf32(acc[mi][ni], alo[mi], bhi);
                mma_tf32(acc[mi][ni], ahi[mi], bhi);
            }
        }
    }

#pragma unroll
    for (int mi = 0; mi < 2; mi++) {
        const int row = mbase + wm + mi * 16 + lrow;
#pragma unroll
        for (int ni = 0; ni < 4; ni++) {
            const int col = nbase + wn + ni * 8 + lcol * 2;
            if (row < R_ROWS)
                *(float2*)&Cb[(size_t)row * T_LEN + col] =
                    make_float2(acc[mi][ni][0], acc[mi][ni][1]);
            if (row + 8 < R_ROWS)
                *(float2*)&Cb[(size_t)(row + 8) * T_LEN + col] =
                    make_float2(acc[mi][ni][2], acc[mi][ni][3]);
        }
    }
}

// ============================================================
// SIMT slab GEMM (used for m2 only):
//   per bz: C[m,n] = sum_{h<64} A[m, z*64+h] * B[n, z*64+h]
// ============================================================
__global__ void __launch_bounds__(256) slab_gemm_kernel(
    const float* __restrict__ A, long sAb, long sAz,
    const float* __restrict__ B, long sBb, long sBz,
    float* __restrict__ C, int ldC, int M, int N)
{
    const int bz = blockIdx.z;
    const int b = bz / NH, z = bz % NH;
    const float* Ab = A + (size_t)b * sAb + (size_t)z * sAz;
    const float* Bb = B + (size_t)b * sBb + (size_t)z * sBz;
    float* Cb = C + (size_t)bz * M * ldC;

    __shared__ float Qs[64][68];
    __shared__ float Ks[64][68];

    const int tid = threadIdx.x;
    const int mbase = blockIdx.y * 64, nbase = blockIdx.x * 64;

#pragma unroll
    for (int i = 0; i < 4; i++) {
        int fl = tid + 256 * i;
        int row = fl >> 4;
        int hc = (fl & 15) * 4;
        float4 v = make_float4(0.f, 0.f, 0.f, 0.f);
        if (mbase + row < M)
            v = *(const float4*)&Ab[(size_t)(mbase + row) * D_MODEL + hc];
        Qs[hc + 0][row] = v.x; Qs[hc + 1][row] = v.y;
        Qs[hc + 2][row] = v.z; Qs[hc + 3][row] = v.w;
    }
#pragma unroll
    for (int i = 0; i < 4; i++) {
        int fl = tid + 256 * i;
        int row = fl >> 4;
        int hc = (fl & 15) * 4;
        float4 v = make_float4(0.f, 0.f, 0.f, 0.f);
        if (nbase + row < N)
            v = *(const float4*)&Bb[(size_t)(nbase + row) * D_MODEL + hc];
        Ks[hc + 0][row] = v.x; Ks[hc + 1][row] = v.y;
        Ks[hc + 2][row] = v.z; Ks[hc + 3][row] = v.w;
    }
    __syncthreads();

    const int tx = tid & 15, ty = tid >> 4;
    float acc[4][4];
#pragma unroll
    for (int i = 0; i < 4; i++)
#pragma unroll
        for (int j = 0; j < 4; j++) acc[i][j] = 0.f;

#pragma unroll
    for (int h = 0; h < 64; h++) {
        float ar[4], br[4];
        *(float4*)&ar[0] = *(float4*)&Qs[h][ty * 4];
        *(float4*)&br[0] = *(float4*)&Ks[h][tx * 4];
#pragma unroll
        for (int i = 0; i < 4; i++)
#pragma unroll
            for (int j = 0; j < 4; j++)
                acc[i][j] = fmaf(ar[i], br[j], acc[i][j]);
    }

#pragma unroll
    for (int i = 0; i < 4; i++) {
        int m = mbase + ty * 4 + i;
        if (m < M) {
#pragma unroll
            for (int j = 0; j < 4; j++) {
                int n = nbase + tx * 4 + j;
                if (n < N) Cb[(size_t)m * ldC + n] = acc[i][j];
            }
        }
    }
}

// ============================================================
// Softmax over t for 4 synonym rows, combine into mean weights
// ============================================================
__global__ void __launch_bounds__(128) softmax_combine_kernel(
    const float* __restrict__ scores, float* __restrict__ w)
{
    __shared__ float ex[4][1024];
    __shared__ float invl[4];
    const int blk = blockIdx.x;          // bz*50 + c
    const int bz = blk / C_CLS, c = blk % C_CLS;
    const int warp = threadIdx.x >> 5, lane = threadIdx.x & 31;

    const float* row = scores + ((size_t)bz * R_ROWS + c * 4 + warp) * T_LEN;

    float m = -INFINITY;
    for (int t = lane; t < T_LEN; t += 32) m = fmaxf(m, row[t]);
#pragma unroll
    for (int o = 16; o > 0; o >>= 1) m = fmaxf(m, __shfl_xor_sync(0xffffffffu, m, o));

    float ssum = 0.f;
    for (int t = lane; t < T_LEN; t += 32) {
        float e = expf(row[t] - m);
        ex[warp][t] = e;
        ssum += e;
    }
#pragma unroll
    for (int o = 16; o > 0; o >>= 1) ssum += __shfl_xor_sync(0xffffffffu, ssum, o);
    if (lane == 0) invl[warp] = 0.25f / ssum;
    __syncthreads();

    float* wr = w + ((size_t)bz * C_CLS + c) * T_LEN;
    for (int t = threadIdx.x; t < T_LEN; t += 128)
        wr[t] = ex[0][t] * invl[0] + ex[1][t] * invl[1]
              + ex[2][t] * invl[2] + ex[3][t] * invl[3];
}

// ============================================================
// tanh elementwise (Kh = tanh(H)), float4 vectorized
// ============================================================
__global__ void __launch_bounds__(256) tanh_kernel(
    const float* __restrict__ in, float* __restrict__ outp, int n4)
{
    int i = blockIdx.x * blockDim.x + threadIdx.x;
    if (i < n4) {
        float4 v = ((const float4*)in)[i];
        v.x = tanhf(v.x); v.y = tanhf(v.y);
        v.z = tanhf(v.z); v.w = tanhf(v.w);
        ((float4*)outp)[i] = v;
    }
}

// ============================================================
// Final: out[b,c] = sum_{z,t} w[bz,c,t] * m2[bz,t,c]
// ============================================================
__global__ void __launch_bounds__(256) final_out_kernel(
    const float* __restrict__ w, const float* __restrict__ m2,
    float* __restrict__ out)
{
    const int blk = blockIdx.x;           // b*50 + c
    const int b = blk / C_CLS, c = blk % C_CLS;
    float acc = 0.f;
    for (int idx = threadIdx.x; idx < NH * T_LEN; idx += 256) {
        int z = idx >> 10, t = idx & 1023;
        int bz = b * NH + z;
        float wv = w [((size_t)bz * C_CLS + c) * T_LEN + t];
        float mv = m2[((size_t)bz * T_LEN + t) * C_CLS + c];
        acc += wv * mv;
    }
    __shared__ float red[256];
    red[threadIdx.x] = acc;
    __syncthreads();
    for (int s = 128; s > 0; s >>= 1) {
        if (threadIdx.x < s) red[threadIdx.x] += red[threadIdx.x + s];
        __syncthreads();
    }
    if (threadIdx.x == 0) out[blk] = red[0];
}

// ============================================================
extern "C" void kernel_launch(void* const* d_in, const int* in_sizes, int n_in,
                              void* d_out, int out_size)
{
    const float* Q   = (const float*)d_in[0];
    const float* H   = (const float*)d_in[1];
    const float* ql  = (const float*)d_in[2];
    const float* WQw = (const float*)d_in[3];
    const float* WQb = (const float*)d_in[4];
    const float* WKw = (const float*)d_in[5];
    const float* WKb = (const float*)d_in[6];
    const float* WVw = (const float*)d_in[7];
    const float* WVb = (const float*)d_in[8];
    float* out = (float*)d_out;

    float *qproj, *kproj, *ktanh, *wql, *scores, *w, *m2;
    cudaGetSymbolAddress((void**)&qproj,  g_qproj);
    cudaGetSymbolAddress((void**)&kproj,  g_kproj);
    cudaGetSymbolAddress((void**)&ktanh,  g_ktanh);
    cudaGetSymbolAddress((void**)&wql,    g_wql);
    cudaGetSymbolAddress((void**)&scores, g_scores);
    cudaGetSymbolAddress((void**)&w,      g_w);
    cudaGetSymbolAddress((void**)&m2,     g_m2);

    // allow large dynamic smem (host-side attribute, idempotent)
    cudaFuncSetAttribute(gemm_tf32_kernel<0>,
                         cudaFuncAttributeMaxDynamicSharedMemorySize, GEMM_SMEM);
    cudaFuncSetAttribute(gemm_tf32_kernel<1>,
                         cudaFuncAttributeMaxDynamicSharedMemorySize, GEMM_SMEM);
    cudaFuncSetAttribute(scores_tf32_kernel,
                         cudaFuncAttributeMaxDynamicSharedMemorySize, SC_SMEM);

    // projections on tensor cores (3xTF32, fp32-accurate)
    gemm_tf32_kernel<0><<<dim3(6, 2),  256, GEMM_SMEM>>>(Q,  WQw, WQb, qproj, R_ROWS, D_MODEL, D_MODEL);
    gemm_tf32_kernel<1><<<dim3(6, 32), 256, GEMM_SMEM>>>(H,  WKw, WKb, kproj, B_BATCH * T_LEN, D_MODEL, D_MODEL);
    gemm_tf32_kernel<0><<<dim3(6, 1),  256, GEMM_SMEM>>>(ql, WVw, WVb, wql,   C_CLS,  D_MODEL, D_MODEL);
    tanh_kernel<<<(B_BATCH * T_LEN * D_MODEL / 4 + 255) / 256, 256>>>(H, ktanh, B_BATCH * T_LEN * D_MODEL / 4);

    // scores[bz][r=200][t=1024] on tensor cores
    scores_tf32_kernel<<<dim3(8, 4, BZ), 256, SC_SMEM>>>(qproj, kproj, scores);

    // softmax over t + combine synonyms into mean weights
    softmax_combine_kernel<<<BZ * C_CLS, 128>>>(scores, w);

    // m2[bz][t=1024][c=50] = ktanh . wql  (over 64-wide head slice)
    slab_gemm_kernel<<<dim3(1, 16, BZ), 256>>>(
        ktanh, (long)T_LEN * D_MODEL, (long)HDIM,
        wql, 0L, (long)HDIM,
        m2, C_CLS, T_LEN, C_CLS);

    // out[b,c] = sum_{z,t} w * m2
    final_out_kernel<<<B_BATCH * C_CLS, 256>>>(w, m2, out);
}